// round 14
// baseline (speedup 1.0000x reference)
#include <cuda_runtime.h>
#include <cuda_fp16.h>
#include <cstdint>

#define P    8192
#define NB   4
#define NPTS 2048
#define Dd   3
#define Cc   64
#define HH   512
#define MT   8
#define TPB  256
#define PTPB 256
#define PMT  16
#define GRID (P/MT)          // 1024
#define PGRID (P/PMT)        // 512
#define EPSBN 1e-4f
#define ASH  520             // A smem row stride (halves)

// ---------------- scratch ----------------
__device__ float g_Gc0[P*HH];
__device__ float g_Gc1[P*HH];
__device__ float g_Gc2[P*HH];
__device__ float g_Gc3[P*Dd];
__device__ float g_Bc0[P*HH];
__device__ float g_Bc1[P*HH];
__device__ float g_Bc2[P*HH];
__device__ float g_Bc3[P*Dd];
__device__ float g_xs[P*Dd];
__device__ float g_lp[P];
// fragment-major packed fp16 weights (same packing as R12)
__device__ __half g_W1p[HH*HH];
__device__ __half g_W2p[HH*HH];

__device__ __forceinline__ float sigf(float z) { return 1.f/(1.f+__expf(-z)); }
__device__ __forceinline__ float htanh(float x) {
    float e = __expf(2.f*x);
    return 1.f - __fdividef(2.f, e + 1.f);
}

#define LDSM4(R0,R1,R2,R3,ADDR) \
    asm volatile("ldmatrix.sync.aligned.m8n8.x4.shared.b16 {%0,%1,%2,%3}, [%4];" \
        : "=r"(R0),"=r"(R1),"=r"(R2),"=r"(R3) : "r"(ADDR))

__device__ __forceinline__ void mma_f16(float* c,
    uint32_t a0, uint32_t a1, uint32_t a2, uint32_t a3, uint32_t b0, uint32_t b1)
{
    asm volatile("mma.sync.aligned.m16n8k16.row.col.f32.f16.f16.f32 "
        "{%0,%1,%2,%3}, {%4,%5,%6,%7}, {%8,%9}, {%0,%1,%2,%3};"
        : "+f"(c[0]), "+f"(c[1]), "+f"(c[2]), "+f"(c[3])
        : "r"(a0), "r"(a1), "r"(a2), "r"(a3), "r"(b0), "r"(b1));
}

// ------------- weight pack (once per launch) -------------
__global__ void __launch_bounds__(TPB) conv_kernel(const float* __restrict__ W1,
                                                   const float* __restrict__ W2)
{
    int idx = blockIdx.x*TPB + threadIdx.x;
    int n  = idx >> 9;
    int r  = idx & 511;
    int kp = r >> 5;
    int tq = (r >> 3) & 3;
    int j  = r & 7;
    int jj = j & 3;
    int k  = kp*32 + ((j>>2)<<4) + 2*tq + (jj&1) + ((jj>>1)<<3);
    g_W1p[idx] = __float2half_rn(W1[n*HH + k]);
    g_W2p[idx] = __float2half_rn(W2[n*HH + k]);
}

// ------------- precompute (unchanged from R12) -------------
__global__ void __launch_bounds__(PTPB) pre_kernel(
    const float* __restrict__ x, const float* __restrict__ c,
    const float* __restrict__ m1, const float* __restrict__ v1,
    const float* __restrict__ lg1, const float* __restrict__ be1,
    const float* __restrict__ Wg0, const float* __restrict__ bg0, const float* __restrict__ Wb0,
    const float* __restrict__ Wg1, const float* __restrict__ bg1, const float* __restrict__ Wb1,
    const float* __restrict__ Wg2, const float* __restrict__ bg2, const float* __restrict__ Wb2,
    const float* __restrict__ Wg3, const float* __restrict__ bg3, const float* __restrict__ Wb3)
{
    __shared__ float cs[PMT][Cc];
    int tid = threadIdx.x;
    int base = blockIdx.x * PMT;
    for (int i = tid; i < PMT*Cc; i += PTPB) cs[i>>6][i&63] = c[base*Cc + i];
    if (tid < PMT*Dd) {
        int m = tid/Dd, d = tid - m*Dd, p = base+m;
        g_xs[p*Dd+d] = (x[p*Dd+d] - m1[d]) * __expf(lg1[d]) * rsqrtf(v1[d]+EPSBN) + be1[d];
    }
    if (tid >= 64 && tid < 64+PMT) {
        int m = tid-64, p = base+m;
        float ld = 0.f;
        #pragma unroll
        for (int d = 0; d < Dd; ++d) ld += lg1[d] - 0.5f*logf(v1[d]+EPSBN);
        g_lp[p] = -ld;
    }
    __syncthreads();

    const float* WGs[3] = {Wg0, Wg1, Wg2};
    const float* BGs[3] = {bg0, bg1, bg2};
    const float* WBs[3] = {Wb0, Wb1, Wb2};
    float* GCs[3] = {g_Gc0, g_Gc1, g_Gc2};
    float* BCs[3] = {g_Bc0, g_Bc1, g_Bc2};
    #pragma unroll
    for (int l = 0; l < 3; ++l) {
        const float* Wg = WGs[l]; const float* Wb = WBs[l];
        #pragma unroll
        for (int s = 0; s < 2; ++s) {
            int j = tid + s*PTPB;
            float ag[PMT], ab[PMT];
            #pragma unroll
            for (int m = 0; m < PMT; ++m) { ag[m]=0.f; ab[m]=0.f; }
            const float* wgr = Wg + j*(Cc+1) + 1;
            const float* wbr = Wb + j*(Cc+1) + 1;
            for (int q = 0; q < Cc; ++q) {
                float a = wgr[q], b = wbr[q];
                #pragma unroll
                for (int m = 0; m < PMT; ++m) { ag[m] += a*cs[m][q]; ab[m] += b*cs[m][q]; }
            }
            float bgj = BGs[l][j];
            float* Gc = GCs[l]; float* Bc = BCs[l];
            for (int m = 0; m < PMT; ++m) {
                int p = base+m;
                Gc[p*HH+j] = ag[m]+bgj; Bc[p*HH+j] = ab[m];
            }
        }
    }
    if (tid < Dd) {
        int j = tid;
        float ag[PMT], ab[PMT];
        #pragma unroll
        for (int m = 0; m < PMT; ++m) { ag[m]=0.f; ab[m]=0.f; }
        const float* wgr = Wg3 + j*(Cc+1) + 1;
        const float* wbr = Wb3 + j*(Cc+1) + 1;
        for (int q = 0; q < Cc; ++q) {
            float a = wgr[q], b = wbr[q];
            #pragma unroll
            for (int m = 0; m < PMT; ++m) { ag[m] += a*cs[m][q]; ab[m] += b*cs[m][q]; }
        }
        for (int m = 0; m < PMT; ++m) {
            int p = base+m;
            g_Gc3[p*Dd+j] = ag[m]+bg3[j]; g_Bc3[p*Dd+j] = ab[m];
        }
    }
}

// ------------- fp16 TC GEMM n-half: C[32 x (4x8 cols)] for nt group ntb..ntb+3 -------------
__device__ __forceinline__ void gemm_h(const __half* __restrict__ Wp,
                                       uint32_t aB, float (&c)[2][4][4],
                                       int ntb, int tid)
{
    const int warp = tid>>5, lane = tid&31;
    const int g = lane>>2, tq = lane&3;
    const int arow = lane & 15, acolo = (lane>>4)*8;
    const __half* bp = Wp + (size_t)(warp*64 + ntb*8 + g)*HH + tq*8;

    #pragma unroll 4
    for (int kp = 0; kp < 16; ++kp) {
        uint4 br[4];
        #pragma unroll
        for (int nt = 0; nt < 4; ++nt)
            br[nt] = *(const uint4*)(bp + (size_t)nt*8*HH + kp*32);
        #pragma unroll
        for (int h = 0; h < 2; ++h) {
            const int kc = 2*kp + h;
            uint32_t a[2][4];
            #pragma unroll
            for (int mt = 0; mt < 2; ++mt) {
                uint32_t addr = aB + (uint32_t)(((mt*16+arow)*ASH) + kc*16 + acolo)*2;
                LDSM4(a[mt][0], a[mt][1], a[mt][2], a[mt][3], addr);
            }
            #pragma unroll
            for (int nt = 0; nt < 4; ++nt) {
                uint32_t b0 = h ? br[nt].z : br[nt].x;
                uint32_t b1 = h ? br[nt].w : br[nt].y;
                #pragma unroll
                for (int mt = 0; mt < 2; ++mt)
                    mma_f16(c[mt][nt], a[mt][0], a[mt][1], a[mt][2], a[mt][3], b0, b1);
            }
        }
    }
}

// ------------- persistent flow kernel: MT=8 points, 2 CTAs/SM -------------
// A tile rows: 0..7 = h(point m) ; 8+8d+m = tangent d of point m.
// C frags: tile0 rows g(h), g+8(t0); tile1 rows g(t1), g+8(t2)  -> all point g, in-thread.
__global__ void __launch_bounds__(TPB, 2) flow_kernel(
    const float* __restrict__ W0, const float* __restrict__ b0,
    const float* __restrict__ Wg0, const float* __restrict__ Wb0,
    const float* __restrict__ b1,
    const float* __restrict__ Wg1, const float* __restrict__ Wb1,
    const float* __restrict__ b2,
    const float* __restrict__ Wg2, const float* __restrict__ Wb2,
    const float* __restrict__ W3, const float* __restrict__ b3,
    const float* __restrict__ Wg3, const float* __restrict__ Wb3,
    const float* __restrict__ sqrtT)
{
    extern __shared__ char smraw[];
    __half* Ah  = (__half*)smraw;            // 32*ASH halves
    float* colc = (float*)(Ah + 32*ASH);     // 9*512
    float* wred = colc + 9*HH;               // 8*48
    float* xin  = wred + 8*48;               // 24
    float* sdx  = xin + 24;
    float* pdg  = sdx + 24;
    float* xs_s = pdg + 24;
    float* ax_s = xs_s + 24;
    float* lp_s = ax_s + 24;                 // 8
    float* al_s = lp_s + 8;                  // 8

    const int tid = threadIdx.x;
    const int warp = tid>>5, lane = tid&31;
    const int g = lane>>2, tq = lane&3;
    const int nb = warp*64;
    const int base = blockIdx.x*MT;
    const uint32_t aB = (uint32_t)__cvta_generic_to_shared(Ah);
    const float sT = sqrtT[0];
    const float dt = sT*sT*(1.f/3.f);

    #pragma unroll
    for (int s = 0; s < 2; ++s) {
        int j = tid + s*TPB;
        colc[0*HH+j] = b1[j];
        colc[1*HH+j] = Wg1[j*65];
        colc[2*HH+j] = Wb1[j*65];
        colc[3*HH+j] = b2[j];
        colc[4*HH+j] = Wg2[j*65];
        colc[5*HH+j] = Wb2[j*65];
        colc[6*HH+j] = W3[j];
        colc[7*HH+j] = W3[HH+j];
        colc[8*HH+j] = W3[2*HH+j];
    }
    if (tid < MT*Dd) { float v = g_xs[base*Dd + tid]; xin[tid] = v; xs_s[tid] = v; }
    if (tid < MT) lp_s[tid] = g_lp[base + tid];
    __syncthreads();

    const int j0 = 2*tid;
    const float wa0 = W0[j0*3], wb0 = W0[j0*3+1], wc0 = W0[j0*3+2];
    const float bj0 = b0[j0], wgt0 = Wg0[j0*65], wbt0 = Wb0[j0*65];
    const float wa1 = W0[j0*3+3], wb1_ = W0[j0*3+4], wc1 = W0[j0*3+5];
    const float bj1 = b0[j0+1], wgt1 = Wg0[(j0+1)*65], wbt1 = Wb0[(j0+1)*65];

    for (int it = 0; it < 12; ++it) {
        const int s = it & 3;
        const float tc = (s == 0) ? 0.f : ((s == 3) ? 1.f : 0.5f);
        const float t = ((float)(it >> 2) + tc) * dt;

        // ---- L0 ----
        #pragma unroll
        for (int m = 0; m < MT; ++m) {
            size_t off = (size_t)(base+m)*HH + j0;
            float x0 = xin[m*3], x1 = xin[m*3+1], x2 = xin[m*3+2];
            float2 gc = *(const float2*)&g_Gc0[off];
            float2 bc = *(const float2*)&g_Bc0[off];
            float z0 = x0*wa0 + x1*wb0 + x2*wc0 + bj0;
            float z1 = x0*wa1 + x1*wb1_ + x2*wc1 + bj1;
            float gg0 = sigf(t*wgt0 + gc.x), gg1 = sigf(t*wgt1 + gc.y);
            float h0 = htanh(z0*gg0 + t*wbt0 + bc.x);
            float h1 = htanh(z1*gg1 + t*wbt1 + bc.y);
            float q0 = (1.f-h0*h0)*gg0, q1 = (1.f-h1*h1)*gg1;
            *(__half2*)(Ah + m*ASH + j0)      = __floats2half2_rn(h0, h1);
            *(__half2*)(Ah + (8+m)*ASH + j0)  = __floats2half2_rn(q0*wa0, q1*wa1);
            *(__half2*)(Ah + (16+m)*ASH + j0) = __floats2half2_rn(q0*wb0, q1*wb1_);
            *(__half2*)(Ah + (24+m)*ASH + j0) = __floats2half2_rn(q0*wc0, q1*wc1);
        }
        __syncthreads();

        float cA[2][4][4], cB[2][4][4];
        #pragma unroll
        for (int a1=0;a1<2;++a1) for (int a2=0;a2<4;++a2) for (int a3=0;a3<4;++a3){ cA[a1][a2][a3]=0.f; cB[a1][a2][a3]=0.f; }
        gemm_h(g_W1p, aB, cA, 0, tid);
        gemm_h(g_W1p, aB, cB, 4, tid);
        __syncthreads();

        // ---- EW1 (point g, all in-thread) ----
        #pragma unroll
        for (int nt = 0; nt < 8; ++nt) {
            float* cf = (nt < 4) ? &cA[0][nt][0] : &cB[0][nt-4][0];     // [0][nt][0..3]
            float* ct = (nt < 4) ? &cA[1][nt][0] : &cB[1][nt-4][0];     // [1][nt][0..3]
            int col0 = nb + nt*8 + 2*tq;
            size_t off = (size_t)(base+g)*HH + col0;
            float2 gc = *(const float2*)&g_Gc1[off];
            float2 bc = *(const float2*)&g_Bc1[off];
            float gate0 = sigf(t*colc[1*HH+col0] + gc.x);
            float gate1 = sigf(t*colc[1*HH+col0+1] + gc.y);
            float h0 = htanh((cf[0]+colc[0*HH+col0])*gate0 + t*colc[2*HH+col0] + bc.x);
            float h1 = htanh((cf[1]+colc[0*HH+col0+1])*gate1 + t*colc[2*HH+col0+1] + bc.y);
            float q0 = (1.f-h0*h0)*gate0, q1 = (1.f-h1*h1)*gate1;
            *(__half2*)(Ah + g*ASH + col0)      = __floats2half2_rn(h0, h1);
            *(__half2*)(Ah + (8+g)*ASH + col0)  = __floats2half2_rn(cf[2]*q0, cf[3]*q1);
            *(__half2*)(Ah + (16+g)*ASH + col0) = __floats2half2_rn(ct[0]*q0, ct[1]*q1);
            *(__half2*)(Ah + (24+g)*ASH + col0) = __floats2half2_rn(ct[2]*q0, ct[3]*q1);
        }
        __syncthreads();

        #pragma unroll
        for (int a1=0;a1<2;++a1) for (int a2=0;a2<4;++a2) for (int a3=0;a3<4;++a3){ cA[a1][a2][a3]=0.f; cB[a1][a2][a3]=0.f; }
        gemm_h(g_W2p, aB, cA, 0, tid);
        gemm_h(g_W2p, aB, cB, 4, tid);

        // ---- EW2 + reduction (point g) ----
        {
            float v[6];
            #pragma unroll
            for (int k = 0; k < 6; ++k) v[k] = 0.f;
            #pragma unroll
            for (int nt = 0; nt < 8; ++nt) {
                float* cf = (nt < 4) ? &cA[0][nt][0] : &cB[0][nt-4][0];
                float* ct = (nt < 4) ? &cA[1][nt][0] : &cB[1][nt-4][0];
                int col0 = nb + nt*8 + 2*tq;
                size_t off = (size_t)(base+g)*HH + col0;
                float2 gc = *(const float2*)&g_Gc2[off];
                float2 bc = *(const float2*)&g_Bc2[off];
                float gate0 = sigf(t*colc[4*HH+col0] + gc.x);
                float gate1 = sigf(t*colc[4*HH+col0+1] + gc.y);
                float h0 = htanh((cf[0]+colc[3*HH+col0])*gate0 + t*colc[5*HH+col0] + bc.x);
                float h1 = htanh((cf[1]+colc[3*HH+col0+1])*gate1 + t*colc[5*HH+col0+1] + bc.y);
                float q0 = (1.f-h0*h0)*gate0, q1 = (1.f-h1*h1)*gate1;
                float tg0[3] = {cf[2], ct[0], ct[2]};
                float tg1[3] = {cf[3], ct[1], ct[3]};
                #pragma unroll
                for (int d = 0; d < 3; ++d) {
                    float w3x = colc[(6+d)*HH+col0], w3y = colc[(6+d)*HH+col0+1];
                    v[d]   += h0*w3x + h1*w3y;
                    v[3+d] += q0*w3x*tg0[d] + q1*w3y*tg1[d];
                }
            }
            #pragma unroll
            for (int k = 0; k < 6; ++k) {
                v[k] += __shfl_xor_sync(0xffffffffu, v[k], 1);
                v[k] += __shfl_xor_sync(0xffffffffu, v[k], 2);
            }
            if (tq == 0) {
                #pragma unroll
                for (int k = 0; k < 6; ++k) wred[warp*48 + g*6 + k] = v[k];
            }
        }
        __syncthreads();

        if (tid < 48) {
            int m = tid/6, k = tid - m*6;
            float sv = 0.f;
            #pragma unroll
            for (int w = 0; w < 8; ++w) sv += wred[w*48 + tid];
            int p = base + m;
            if (k < 3) {
                float g3 = sigf(t*Wg3[k*65] + g_Gc3[p*3+k]);
                sdx[m*3+k] = (sv + b3[k])*g3 + t*Wb3[k*65] + g_Bc3[p*3+k];
            } else {
                int d = k-3;
                float g3 = sigf(t*Wg3[d*65] + g_Gc3[p*3+d]);
                pdg[m*3+d] = sv*g3;
            }
        }
        __syncthreads();

        if (tid < MT) {
            int m = tid;
            float kl = -(pdg[m*3] + pdg[m*3+1] + pdg[m*3+2]);
            if (s == 0) {
                al_s[m] = kl;
                #pragma unroll
                for (int d = 0; d < 3; ++d) {
                    float kx = sdx[m*3+d];
                    ax_s[m*3+d] = kx;
                    xin[m*3+d] = xs_s[m*3+d] + 0.5f*dt*kx;
                }
            } else if (s == 1) {
                al_s[m] += 2.f*kl;
                #pragma unroll
                for (int d = 0; d < 3; ++d) {
                    float kx = sdx[m*3+d];
                    ax_s[m*3+d] += 2.f*kx;
                    xin[m*3+d] = xs_s[m*3+d] + 0.5f*dt*kx;
                }
            } else if (s == 2) {
                al_s[m] += 2.f*kl;
                #pragma unroll
                for (int d = 0; d < 3; ++d) {
                    float kx = sdx[m*3+d];
                    ax_s[m*3+d] += 2.f*kx;
                    xin[m*3+d] = xs_s[m*3+d] + dt*kx;
                }
            } else {
                float c6 = dt*(1.f/6.f);
                lp_s[m] += c6*(al_s[m] + kl);
                #pragma unroll
                for (int d = 0; d < 3; ++d) {
                    float nv = xs_s[m*3+d] + c6*(ax_s[m*3+d] + sdx[m*3+d]);
                    xs_s[m*3+d] = nv;
                    xin[m*3+d] = nv;
                }
            }
        }
        __syncthreads();
    }

    if (tid < MT*Dd) g_xs[base*Dd + tid] = xs_s[tid];
    if (tid < MT) g_lp[base + tid] = lp_s[tid];
}

// ------------- bn2 + per-batch logp reduction + output -------------
__global__ void __launch_bounds__(PTPB) final_kernel(
    const float* __restrict__ m2, const float* __restrict__ v2,
    const float* __restrict__ lg2, const float* __restrict__ be2,
    float* __restrict__ out)
{
    __shared__ float red[PTPB];
    int b = blockIdx.x, tid = threadIdx.x;
    float sc[3], mn[3], bt[3];
    float ld2 = 0.f;
    #pragma unroll
    for (int d = 0; d < 3; ++d) {
        sc[d] = __expf(lg2[d]) * rsqrtf(v2[d]+EPSBN);
        mn[d] = m2[d]; bt[d] = be2[d];
        ld2 += lg2[d] - 0.5f*logf(v2[d]+EPSBN);
    }
    float part = 0.f;
    for (int n = tid; n < NPTS; n += PTPB) {
        int p = b*NPTS + n;
        #pragma unroll
        for (int d = 0; d < 3; ++d)
            out[p*3+d] = (g_xs[p*3+d]-mn[d])*sc[d] + bt[d];
        part += g_lp[p] - ld2;
    }
    red[tid] = part;
    __syncthreads();
    for (int off = PTPB/2; off > 0; off >>= 1) {
        if (tid < off) red[tid] += red[tid+off];
        __syncthreads();
    }
    if (tid == 0) out[P*3 + b] = red[0];
}

// ---------------- launch ----------------
extern "C" void kernel_launch(void* const* d_in, const int* in_sizes, int n_in,
                              void* d_out, int out_size)
{
    const float* x    = (const float*)d_in[0];
    const float* c    = (const float*)d_in[1];
    const float* bn1m = (const float*)d_in[2];
    const float* bn1v = (const float*)d_in[3];
    const float* bn1g = (const float*)d_in[4];
    const float* bn1b = (const float*)d_in[5];
    const float* bn2m = (const float*)d_in[6];
    const float* bn2v = (const float*)d_in[7];
    const float* bn2g = (const float*)d_in[8];
    const float* bn2b = (const float*)d_in[9];
    const float* sqT  = (const float*)d_in[10];
    const float *W[4], *bb[4], *Wg[4], *bg[4], *Wb[4];
    for (int i = 0; i < 4; ++i) {
        W[i]  = (const float*)d_in[11+5*i];
        bb[i] = (const float*)d_in[12+5*i];
        Wg[i] = (const float*)d_in[13+5*i];
        bg[i] = (const float*)d_in[14+5*i];
        Wb[i] = (const float*)d_in[15+5*i];
    }

    int smem = (32*ASH)*2 + (9*HH + 8*48 + 24*5 + 8*2)*4;
    cudaFuncSetAttribute(flow_kernel, cudaFuncAttributeMaxDynamicSharedMemorySize, smem);

    conv_kernel<<<HH*HH/TPB, TPB>>>(W[1], W[2]);
    pre_kernel<<<PGRID, PTPB>>>(x, c, bn1m, bn1v, bn1g, bn1b,
                                Wg[0], bg[0], Wb[0], Wg[1], bg[1], Wb[1],
                                Wg[2], bg[2], Wb[2], Wg[3], bg[3], Wb[3]);
    flow_kernel<<<GRID, TPB, smem>>>(
        W[0], bb[0], Wg[0], Wb[0],
        bb[1], Wg[1], Wb[1],
        bb[2], Wg[2], Wb[2],
        W[3], bb[3], Wg[3], Wb[3],
        sqT);
    final_kernel<<<NB, PTPB>>>(bn2m, bn2v, bn2g, bn2b, (float*)d_out);
}

// round 16
// speedup vs baseline: 1.2309x; 1.2309x over previous
#include <cuda_runtime.h>
#include <cuda_fp16.h>
#include <cstdint>

#define P    8192
#define NB   4
#define NPTS 2048
#define Dd   3
#define Cc   64
#define HH   512
#define MT   16
#define TPB  512
#define PTPB 256
#define PMT  16
#define GRID (P/MT)          // 512
#define PGRID (P/PMT)        // 512
#define EPSBN 1e-4f
#define ASH  520             // A smem row stride (halves)
#define GSH  520             // gate-table smem row stride (floats)
#define GBUF (32*GSH)        // one buffer: Gc tile (16 rows) + Bc tile (16 rows)

// ---------------- scratch ----------------
__device__ float g_Gc0[P*HH];
__device__ float g_Gc1[P*HH];
__device__ float g_Gc2[P*HH];
__device__ float g_Gc3[P*Dd];
__device__ float g_Bc0[P*HH];
__device__ float g_Bc1[P*HH];
__device__ float g_Bc2[P*HH];
__device__ float g_Bc3[P*Dd];
__device__ float g_xs[P*Dd];
__device__ float g_lp[P];
// fragment-major packed fp16 weights (same packing as R12)
__device__ __half g_W1p[HH*HH];
__device__ __half g_W2p[HH*HH];

__device__ __forceinline__ float sigf(float z) { return 1.f/(1.f+__expf(-z)); }
__device__ __forceinline__ float htanh(float x) {
    float e = __expf(2.f*x);
    return 1.f - __fdividef(2.f, e + 1.f);
}

#define LDSM4(R0,R1,R2,R3,ADDR) \
    asm volatile("ldmatrix.sync.aligned.m8n8.x4.shared.b16 {%0,%1,%2,%3}, [%4];" \
        : "=r"(R0),"=r"(R1),"=r"(R2),"=r"(R3) : "r"(ADDR))
#define CPA(DST,SRC) asm volatile("cp.async.cg.shared.global [%0], [%1], 16;" ::"r"(DST),"l"(SRC))
#define CPC()        asm volatile("cp.async.commit_group;")
#define CPW0()       asm volatile("cp.async.wait_group 0;")

__device__ __forceinline__ void mma_f16(float* c,
    uint32_t a0, uint32_t a1, uint32_t a2, uint32_t a3, uint32_t b0, uint32_t b1)
{
    asm volatile("mma.sync.aligned.m16n8k16.row.col.f32.f16.f16.f32 "
        "{%0,%1,%2,%3}, {%4,%5,%6,%7}, {%8,%9}, {%0,%1,%2,%3};"
        : "+f"(c[0]), "+f"(c[1]), "+f"(c[2]), "+f"(c[3])
        : "r"(a0), "r"(a1), "r"(a2), "r"(a3), "r"(b0), "r"(b1));
}

// prefetch 16x512 float tile pair (Gc, Bc) into smem buffer with row stride GSH
__device__ __forceinline__ void pf_pair(uint32_t dstB, const float* __restrict__ gc,
                                        const float* __restrict__ bc, int tid)
{
    int row = tid>>5, c4 = tid&31;
    uint32_t d0 = dstB + (uint32_t)(row*GSH)*4 + c4*16;
    uint32_t d1 = dstB + (uint32_t)((16+row)*GSH)*4 + c4*16;
    const float4* s0 = (const float4*)(gc + row*HH) + c4;
    const float4* s1 = (const float4*)(bc + row*HH) + c4;
    #pragma unroll
    for (int r = 0; r < 4; ++r) {
        CPA(d0 + r*32*16, s0 + r*32);
        CPA(d1 + r*32*16, s1 + r*32);
    }
}

// ------------- weight pack (once per launch) -------------
__global__ void __launch_bounds__(TPB) conv_kernel(const float* __restrict__ W1,
                                                   const float* __restrict__ W2)
{
    int idx = blockIdx.x*TPB + threadIdx.x;
    int n  = idx >> 9;
    int r  = idx & 511;
    int kp = r >> 5;
    int tq = (r >> 3) & 3;
    int j  = r & 7;
    int jj = j & 3;
    int k  = kp*32 + ((j>>2)<<4) + 2*tq + (jj&1) + ((jj>>1)<<3);
    g_W1p[idx] = __float2half_rn(W1[n*HH + k]);
    g_W2p[idx] = __float2half_rn(W2[n*HH + k]);
}

// ------------- precompute (unchanged) -------------
__global__ void __launch_bounds__(PTPB) pre_kernel(
    const float* __restrict__ x, const float* __restrict__ c,
    const float* __restrict__ m1, const float* __restrict__ v1,
    const float* __restrict__ lg1, const float* __restrict__ be1,
    const float* __restrict__ Wg0, const float* __restrict__ bg0, const float* __restrict__ Wb0,
    const float* __restrict__ Wg1, const float* __restrict__ bg1, const float* __restrict__ Wb1,
    const float* __restrict__ Wg2, const float* __restrict__ bg2, const float* __restrict__ Wb2,
    const float* __restrict__ Wg3, const float* __restrict__ bg3, const float* __restrict__ Wb3)
{
    __shared__ float cs[PMT][Cc];
    int tid = threadIdx.x;
    int base = blockIdx.x * PMT;
    for (int i = tid; i < PMT*Cc; i += PTPB) cs[i>>6][i&63] = c[base*Cc + i];
    if (tid < PMT*Dd) {
        int m = tid/Dd, d = tid - m*Dd, p = base+m;
        g_xs[p*Dd+d] = (x[p*Dd+d] - m1[d]) * __expf(lg1[d]) * rsqrtf(v1[d]+EPSBN) + be1[d];
    }
    if (tid >= 64 && tid < 64+PMT) {
        int m = tid-64, p = base+m;
        float ld = 0.f;
        #pragma unroll
        for (int d = 0; d < Dd; ++d) ld += lg1[d] - 0.5f*logf(v1[d]+EPSBN);
        g_lp[p] = -ld;
    }
    __syncthreads();

    const float* WGs[3] = {Wg0, Wg1, Wg2};
    const float* BGs[3] = {bg0, bg1, bg2};
    const float* WBs[3] = {Wb0, Wb1, Wb2};
    float* GCs[3] = {g_Gc0, g_Gc1, g_Gc2};
    float* BCs[3] = {g_Bc0, g_Bc1, g_Bc2};
    #pragma unroll
    for (int l = 0; l < 3; ++l) {
        const float* Wg = WGs[l]; const float* Wb = WBs[l];
        #pragma unroll
        for (int s = 0; s < 2; ++s) {
            int j = tid + s*PTPB;
            float ag[PMT], ab[PMT];
            #pragma unroll
            for (int m = 0; m < PMT; ++m) { ag[m]=0.f; ab[m]=0.f; }
            const float* wgr = Wg + j*(Cc+1) + 1;
            const float* wbr = Wb + j*(Cc+1) + 1;
            for (int q = 0; q < Cc; ++q) {
                float a = wgr[q], b = wbr[q];
                #pragma unroll
                for (int m = 0; m < PMT; ++m) { ag[m] += a*cs[m][q]; ab[m] += b*cs[m][q]; }
            }
            float bgj = BGs[l][j];
            float* Gc = GCs[l]; float* Bc = BCs[l];
            for (int m = 0; m < PMT; ++m) {
                int p = base+m;
                Gc[p*HH+j] = ag[m]+bgj; Bc[p*HH+j] = ab[m];
            }
        }
    }
    if (tid < Dd) {
        int j = tid;
        float ag[PMT], ab[PMT];
        #pragma unroll
        for (int m = 0; m < PMT; ++m) { ag[m]=0.f; ab[m]=0.f; }
        const float* wgr = Wg3 + j*(Cc+1) + 1;
        const float* wbr = Wb3 + j*(Cc+1) + 1;
        for (int q = 0; q < Cc; ++q) {
            float a = wgr[q], b = wbr[q];
            #pragma unroll
            for (int m = 0; m < PMT; ++m) { ag[m] += a*cs[m][q]; ab[m] += b*cs[m][q]; }
        }
        for (int m = 0; m < PMT; ++m) {
            int p = base+m;
            g_Gc3[p*Dd+j] = ag[m]+bg3[j]; g_Bc3[p*Dd+j] = ab[m];
        }
    }
}

// ------------- fp16 TC GEMM (R12, barrier-free internally) -------------
__device__ __forceinline__ void gemm_f16(const __half* __restrict__ Wp,
                                         uint32_t aB, float c[4][4][4], int tid)
{
    const int warp = tid>>5, lane = tid&31;
    const int g = lane>>2, tq = lane&3;
    const int arow = lane & 15, acolo = (lane>>4)*8;
    const __half* bp = Wp + (size_t)(warp*32 + g)*HH + tq*8;

    #pragma unroll 4
    for (int kp = 0; kp < 16; ++kp) {
        uint4 br[4];
        #pragma unroll
        for (int nt = 0; nt < 4; ++nt)
            br[nt] = *(const uint4*)(bp + (size_t)nt*8*HH + kp*32);
        #pragma unroll
        for (int h = 0; h < 2; ++h) {
            const int kc = 2*kp + h;
            uint32_t a[4][4];
            #pragma unroll
            for (int mt = 0; mt < 4; ++mt) {
                uint32_t addr = aB + (uint32_t)(((mt*16+arow)*ASH) + kc*16 + acolo)*2;
                LDSM4(a[mt][0], a[mt][1], a[mt][2], a[mt][3], addr);
            }
            #pragma unroll
            for (int nt = 0; nt < 4; ++nt) {
                uint32_t b0 = h ? br[nt].z : br[nt].x;
                uint32_t b1 = h ? br[nt].w : br[nt].y;
                #pragma unroll
                for (int mt = 0; mt < 4; ++mt)
                    mma_f16(c[mt][nt], a[mt][0], a[mt][1], a[mt][2], a[mt][3], b0, b1);
            }
        }
    }
}

// ------------- persistent flow kernel -------------
__global__ void __launch_bounds__(TPB, 1) flow_kernel(
    const float* __restrict__ W0, const float* __restrict__ b0,
    const float* __restrict__ Wg0, const float* __restrict__ Wb0,
    const float* __restrict__ b1,
    const float* __restrict__ Wg1, const float* __restrict__ Wb1,
    const float* __restrict__ b2,
    const float* __restrict__ Wg2, const float* __restrict__ Wb2,
    const float* __restrict__ W3, const float* __restrict__ b3,
    const float* __restrict__ Wg3, const float* __restrict__ Wb3,
    const float* __restrict__ sqrtT)
{
    extern __shared__ char smraw[];
    __half* Ah  = (__half*)smraw;            // 64*ASH halves
    float* gbuf = (float*)(Ah + 64*ASH);     // 2 * GBUF floats (gate-table dbl buffer)
    float* colc = gbuf + 2*GBUF;             // 9*512
    float* wred = colc + 9*HH;               // 16*96
    float* xin  = wred + 16*96;              // 48
    float* sdx  = xin + 48;
    float* pdg  = sdx + 48;
    float* xs_s = pdg + 48;
    float* ax_s = xs_s + 48;
    float* lp_s = ax_s + 48;                 // 16
    float* al_s = lp_s + 16;                 // 16

    const int tid = threadIdx.x;
    const int warp = tid>>5, lane = tid&31;
    const int g = lane>>2, tq = lane&3;
    const int nb = warp*32;
    const int base = blockIdx.x*MT;
    const uint32_t aB = (uint32_t)__cvta_generic_to_shared(Ah);
    const uint32_t gB = (uint32_t)__cvta_generic_to_shared(gbuf);
    const float sT = sqrtT[0];
    const float dt = sT*sT*(1.f/3.f);

    colc[0*HH+tid] = b1[tid];
    colc[1*HH+tid] = Wg1[tid*65];
    colc[2*HH+tid] = Wb1[tid*65];
    colc[3*HH+tid] = b2[tid];
    colc[4*HH+tid] = Wg2[tid*65];
    colc[5*HH+tid] = Wb2[tid*65];
    colc[6*HH+tid] = W3[tid];
    colc[7*HH+tid] = W3[HH+tid];
    colc[8*HH+tid] = W3[2*HH+tid];
    if (tid < MT*Dd) { float v = g_xs[base*Dd + tid]; xin[tid] = v; xs_s[tid] = v; }
    if (tid < MT) lp_s[tid] = g_lp[base + tid];

    // prefetch iter-0 L0 tables into buf 0
    pf_pair(gB, g_Gc0 + (size_t)base*HH, g_Bc0 + (size_t)base*HH, tid); CPC();
    CPW0();
    __syncthreads();

    int ping = 0;
    for (int it = 0; it < 12; ++it) {
        const int s = it & 3;
        const float tc = (s == 0) ? 0.f : ((s == 3) ? 1.f : 0.5f);
        const float t = ((float)(it >> 2) + tc) * dt;
        float* bufL = gbuf + ping*GBUF;        // L0 + EW2 tables live here this iter
        float* bufE = gbuf + (1-ping)*GBUF;    // EW1 tables
        uint32_t bufLB = gB + ping*GBUF*4;
        uint32_t bufEB = gB + (1-ping)*GBUF*4;

        // ---- L0 (gate tables from smem) ----
        {
            int j = tid;
            float wa = W0[j*3], wb = W0[j*3+1], wc = W0[j*3+2];
            float bj = b0[j], wgt = Wg0[j*65], wbt = Wb0[j*65];
            #pragma unroll 4
            for (int m = 0; m < MT; ++m) {
                float z = xin[m*3]*wa + xin[m*3+1]*wb + xin[m*3+2]*wc + bj;
                float gg = sigf(t*wgt + bufL[m*GSH + j]);
                float hv = htanh(z*gg + t*wbt + bufL[(16+m)*GSH + j]);
                float qq = (1.f - hv*hv)*gg;
                Ah[m*ASH + j]      = __float2half_rn(hv);
                Ah[(16+m)*ASH + j] = __float2half_rn(qq*wa);
                Ah[(32+m)*ASH + j] = __float2half_rn(qq*wb);
                Ah[(48+m)*ASH + j] = __float2half_rn(qq*wc);
            }
        }
        pf_pair(bufEB, g_Gc1 + (size_t)base*HH, g_Bc1 + (size_t)base*HH, tid); CPC();
        __syncthreads();

        float c[4][4][4];
        #pragma unroll
        for (int a1=0;a1<4;++a1) for (int a2=0;a2<4;++a2) for (int a3=0;a3<4;++a3) c[a1][a2][a3]=0.f;
        gemm_f16(g_W1p, aB, c, tid);
        CPW0();
        __syncthreads();

        // ---- EW1 (gate tables from smem) ----
        #pragma unroll
        for (int nt = 0; nt < 4; ++nt) {
            int col0 = nb + nt*8 + 2*tq;
            float bc0 = colc[0*HH+col0], bc1 = colc[0*HH+col0+1];
            float wg0 = colc[1*HH+col0], wg1v = colc[1*HH+col0+1];
            float wb0 = colc[2*HH+col0], wb1v = colc[2*HH+col0+1];
            #pragma unroll
            for (int kh = 0; kh < 2; ++kh) {
                int m = g + kh*8;
                float2 gc = *(const float2*)&bufE[m*GSH + col0];
                float2 bc = *(const float2*)&bufE[(16+m)*GSH + col0];
                float gate0 = sigf(t*wg0 + gc.x);
                float gate1 = sigf(t*wg1v + gc.y);
                float h0 = htanh((c[0][nt][kh*2]  +bc0)*gate0 + t*wb0  + bc.x);
                float h1 = htanh((c[0][nt][kh*2+1]+bc1)*gate1 + t*wb1v + bc.y);
                float q0 = (1.f-h0*h0)*gate0, q1 = (1.f-h1*h1)*gate1;
                *(__half2*)(Ah + m*ASH + col0) = __floats2half2_rn(h0, h1);
                #pragma unroll
                for (int d = 0; d < 3; ++d)
                    *(__half2*)(Ah + (16+16*d+m)*ASH + col0) =
                        __floats2half2_rn(c[1+d][nt][kh*2]*q0, c[1+d][nt][kh*2+1]*q1);
            }
        }
        pf_pair(bufLB, g_Gc2 + (size_t)base*HH, g_Bc2 + (size_t)base*HH, tid); CPC();
        __syncthreads();

        #pragma unroll
        for (int a1=0;a1<4;++a1) for (int a2=0;a2<4;++a2) for (int a3=0;a3<4;++a3) c[a1][a2][a3]=0.f;
        gemm_f16(g_W2p, aB, c, tid);
        CPW0();
        __syncthreads();

        // ---- EW2 (gate tables from smem) + reductions ----
        {
            float v[12];
            #pragma unroll
            for (int k = 0; k < 12; ++k) v[k] = 0.f;
            #pragma unroll
            for (int nt = 0; nt < 4; ++nt) {
                int col0 = nb + nt*8 + 2*tq;
                float bc0 = colc[3*HH+col0], bc1 = colc[3*HH+col0+1];
                float wg0 = colc[4*HH+col0], wg1v = colc[4*HH+col0+1];
                float wb0 = colc[5*HH+col0], wb1v = colc[5*HH+col0+1];
                float2 w3p[3];
                #pragma unroll
                for (int d = 0; d < 3; ++d) w3p[d] = *(const float2*)&colc[(6+d)*HH+col0];
                #pragma unroll
                for (int kh = 0; kh < 2; ++kh) {
                    int m = g + kh*8;
                    float2 gc = *(const float2*)&bufL[m*GSH + col0];
                    float2 bc = *(const float2*)&bufL[(16+m)*GSH + col0];
                    float gate0 = sigf(t*wg0 + gc.x);
                    float gate1 = sigf(t*wg1v + gc.y);
                    float h0 = htanh((c[0][nt][kh*2]  +bc0)*gate0 + t*wb0  + bc.x);
                    float h1 = htanh((c[0][nt][kh*2+1]+bc1)*gate1 + t*wb1v + bc.y);
                    float q0 = (1.f-h0*h0)*gate0, q1 = (1.f-h1*h1)*gate1;
                    #pragma unroll
                    for (int d = 0; d < 3; ++d) {
                        v[kh*6+d]   += h0*w3p[d].x + h1*w3p[d].y;
                        v[kh*6+3+d] += q0*w3p[d].x*c[1+d][nt][kh*2]
                                     + q1*w3p[d].y*c[1+d][nt][kh*2+1];
                    }
                }
            }
            #pragma unroll
            for (int k = 0; k < 12; ++k) {
                v[k] += __shfl_xor_sync(0xffffffffu, v[k], 1);
                v[k] += __shfl_xor_sync(0xffffffffu, v[k], 2);
            }
            if (tq == 0) {
                #pragma unroll
                for (int k = 0; k < 6; ++k) {
                    wred[warp*96 + g*6 + k]     = v[k];
                    wred[warp*96 + (g+8)*6 + k] = v[6+k];
                }
            }
        }
        if (it < 11) {  // prefetch next iteration's L0 tables into the EW1 buffer slot
            pf_pair(bufEB, g_Gc0 + (size_t)base*HH, g_Bc0 + (size_t)base*HH, tid); CPC();
        }
        __syncthreads();

        if (tid < 96) {
            int m = tid/6, k = tid - m*6;
            float sv = 0.f;
            #pragma unroll
            for (int w = 0; w < 16; ++w) sv += wred[w*96 + tid];
            int p = base + m;
            if (k < 3) {
                int d = k;
                float g3 = sigf(t*Wg3[d*65] + g_Gc3[p*3+d]);
                sdx[m*3+d] = (sv + b3[d])*g3 + t*Wb3[d*65] + g_Bc3[p*3+d];
            } else {
                int d = k-3;
                float g3 = sigf(t*Wg3[d*65] + g_Gc3[p*3+d]);
                pdg[m*3+d] = sv*g3;
            }
        }
        __syncthreads();

        if (tid < MT) {
            int m = tid;
            float kl = -(pdg[m*3] + pdg[m*3+1] + pdg[m*3+2]);
            if (s == 0) {
                al_s[m] = kl;
                #pragma unroll
                for (int d = 0; d < 3; ++d) {
                    float kx = sdx[m*3+d];
                    ax_s[m*3+d] = kx;
                    xin[m*3+d] = xs_s[m*3+d] + 0.5f*dt*kx;
                }
            } else if (s == 1) {
                al_s[m] += 2.f*kl;
                #pragma unroll
                for (int d = 0; d < 3; ++d) {
                    float kx = sdx[m*3+d];
                    ax_s[m*3+d] += 2.f*kx;
                    xin[m*3+d] = xs_s[m*3+d] + 0.5f*dt*kx;
                }
            } else if (s == 2) {
                al_s[m] += 2.f*kl;
                #pragma unroll
                for (int d = 0; d < 3; ++d) {
                    float kx = sdx[m*3+d];
                    ax_s[m*3+d] += 2.f*kx;
                    xin[m*3+d] = xs_s[m*3+d] + dt*kx;
                }
            } else {
                float c6 = dt*(1.f/6.f);
                lp_s[m] += c6*(al_s[m] + kl);
                #pragma unroll
                for (int d = 0; d < 3; ++d) {
                    float nv = xs_s[m*3+d] + c6*(ax_s[m*3+d] + sdx[m*3+d]);
                    xs_s[m*3+d] = nv;
                    xin[m*3+d] = nv;
                }
            }
        }
        if (it < 11) CPW0();
        __syncthreads();
        ping ^= 1;
    }

    if (tid < MT*Dd) g_xs[base*Dd + tid] = xs_s[tid];
    if (tid < MT) g_lp[base + tid] = lp_s[tid];
}

// ------------- bn2 + per-batch logp reduction + output -------------
__global__ void __launch_bounds__(PTPB) final_kernel(
    const float* __restrict__ m2, const float* __restrict__ v2,
    const float* __restrict__ lg2, const float* __restrict__ be2,
    float* __restrict__ out)
{
    __shared__ float red[PTPB];
    int b = blockIdx.x, tid = threadIdx.x;
    float sc[3], mn[3], bt[3];
    float ld2 = 0.f;
    #pragma unroll
    for (int d = 0; d < 3; ++d) {
        sc[d] = __expf(lg2[d]) * rsqrtf(v2[d]+EPSBN);
        mn[d] = m2[d]; bt[d] = be2[d];
        ld2 += lg2[d] - 0.5f*logf(v2[d]+EPSBN);
    }
    float part = 0.f;
    for (int n = tid; n < NPTS; n += PTPB) {
        int p = b*NPTS + n;
        #pragma unroll
        for (int d = 0; d < 3; ++d)
            out[p*3+d] = (g_xs[p*3+d]-mn[d])*sc[d] + bt[d];
        part += g_lp[p] - ld2;
    }
    red[tid] = part;
    __syncthreads();
    for (int off = PTPB/2; off > 0; off >>= 1) {
        if (tid < off) red[tid] += red[tid+off];
        __syncthreads();
    }
    if (tid == 0) out[P*3 + b] = red[0];
}

// ---------------- launch ----------------
extern "C" void kernel_launch(void* const* d_in, const int* in_sizes, int n_in,
                              void* d_out, int out_size)
{
    const float* x    = (const float*)d_in[0];
    const float* c    = (const float*)d_in[1];
    const float* bn1m = (const float*)d_in[2];
    const float* bn1v = (const float*)d_in[3];
    const float* bn1g = (const float*)d_in[4];
    const float* bn1b = (const float*)d_in[5];
    const float* bn2m = (const float*)d_in[6];
    const float* bn2v = (const float*)d_in[7];
    const float* bn2g = (const float*)d_in[8];
    const float* bn2b = (const float*)d_in[9];
    const float* sqT  = (const float*)d_in[10];
    const float *W[4], *bb[4], *Wg[4], *bg[4], *Wb[4];
    for (int i = 0; i < 4; ++i) {
        W[i]  = (const float*)d_in[11+5*i];
        bb[i] = (const float*)d_in[12+5*i];
        Wg[i] = (const float*)d_in[13+5*i];
        bg[i] = (const float*)d_in[14+5*i];
        Wb[i] = (const float*)d_in[15+5*i];
    }

    int smem = (64*ASH)*2 + (2*GBUF + 9*HH + 16*96 + 48*5 + 16*2)*4;
    cudaFuncSetAttribute(flow_kernel, cudaFuncAttributeMaxDynamicSharedMemorySize, smem);

    conv_kernel<<<HH*HH/TPB, TPB>>>(W[1], W[2]);
    pre_kernel<<<PGRID, PTPB>>>(x, c, bn1m, bn1v, bn1g, bn1b,
                                Wg[0], bg[0], Wb[0], Wg[1], bg[1], Wb[1],
                                Wg[2], bg[2], Wb[2], Wg[3], bg[3], Wb[3]);
    flow_kernel<<<GRID, TPB, smem>>>(
        W[0], bb[0], Wg[0], Wb[0],
        bb[1], Wg[1], Wb[1],
        bb[2], Wg[2], Wb[2],
        W[3], bb[3], Wg[3], Wb[3],
        sqT);
    final_kernel<<<NB, PTPB>>>(bn2m, bn2v, bn2g, bn2b, (float*)d_out);
}

// round 17
// speedup vs baseline: 1.3968x; 1.1347x over previous
#include <cuda_runtime.h>
#include <cuda_fp16.h>
#include <cstdint>

#define P    8192
#define NB   4
#define NPTS 2048
#define Dd   3
#define Cc   64
#define HH   512
#define MT   16
#define TPB  512
#define PTPB 256
#define PMT  16
#define GRID (P/MT)          // 512
#define PGRID (P/PMT)        // 512
#define EPSBN 1e-4f
#define ASH  520             // A smem row stride (halves)
#define GSH  520             // gate-table smem row stride (floats)
#define GBUF (32*GSH)        // one buffer: Gc tile (16 rows) + Bc tile (16 rows)

// ---------------- scratch ----------------
__device__ float g_Gc0[P*HH];
__device__ float g_Gc1[P*HH];
__device__ float g_Gc2[P*HH];
__device__ float g_Gc3[P*Dd];
__device__ float g_Bc0[P*HH];
__device__ float g_Bc1[P*HH];
__device__ float g_Bc2[P*HH];
__device__ float g_Bc3[P*Dd];
__device__ float g_xs[P*Dd];
__device__ float g_lp[P];
__device__ __half g_W1p[HH*HH];
__device__ __half g_W2p[HH*HH];

__device__ __forceinline__ float tfast(float x) {
    float y; asm("tanh.approx.f32 %0, %1;" : "=f"(y) : "f"(x)); return y;
}
__device__ __forceinline__ float sigf(float z) { return fmaf(0.5f, tfast(0.5f*z), 0.5f); }
__device__ __forceinline__ float htanh(float x) { return tfast(x); }

#define LDSM4(R0,R1,R2,R3,ADDR) \
    asm volatile("ldmatrix.sync.aligned.m8n8.x4.shared.b16 {%0,%1,%2,%3}, [%4];" \
        : "=r"(R0),"=r"(R1),"=r"(R2),"=r"(R3) : "r"(ADDR))
#define CPA(DST,SRC) asm volatile("cp.async.cg.shared.global [%0], [%1], 16;" ::"r"(DST),"l"(SRC))
#define CPC()        asm volatile("cp.async.commit_group;")
#define CPW0()       asm volatile("cp.async.wait_group 0;")

__device__ __forceinline__ void mma_f16(float* c,
    uint32_t a0, uint32_t a1, uint32_t a2, uint32_t a3, uint32_t b0, uint32_t b1)
{
    asm volatile("mma.sync.aligned.m16n8k16.row.col.f32.f16.f16.f32 "
        "{%0,%1,%2,%3}, {%4,%5,%6,%7}, {%8,%9}, {%0,%1,%2,%3};"
        : "+f"(c[0]), "+f"(c[1]), "+f"(c[2]), "+f"(c[3])
        : "r"(a0), "r"(a1), "r"(a2), "r"(a3), "r"(b0), "r"(b1));
}

__device__ __forceinline__ void pf_pair(uint32_t dstB, const float* __restrict__ gc,
                                        const float* __restrict__ bc, int tid)
{
    int row = tid>>5, c4 = tid&31;
    uint32_t d0 = dstB + (uint32_t)(row*GSH)*4 + c4*16;
    uint32_t d1 = dstB + (uint32_t)((16+row)*GSH)*4 + c4*16;
    const float4* s0 = (const float4*)(gc + row*HH) + c4;
    const float4* s1 = (const float4*)(bc + row*HH) + c4;
    #pragma unroll
    for (int r = 0; r < 4; ++r) {
        CPA(d0 + r*32*16, s0 + r*32);
        CPA(d1 + r*32*16, s1 + r*32);
    }
}

// ------------- weight pack (once per launch) -------------
__global__ void __launch_bounds__(TPB) conv_kernel(const float* __restrict__ W1,
                                                   const float* __restrict__ W2)
{
    int idx = blockIdx.x*TPB + threadIdx.x;
    int n  = idx >> 9;
    int r  = idx & 511;
    int kp = r >> 5;
    int tq = (r >> 3) & 3;
    int j  = r & 7;
    int jj = j & 3;
    int k  = kp*32 + ((j>>2)<<4) + 2*tq + (jj&1) + ((jj>>1)<<3);
    g_W1p[idx] = __float2half_rn(W1[n*HH + k]);
    g_W2p[idx] = __float2half_rn(W2[n*HH + k]);
}

// ------------- precompute (unchanged; full-precision math) -------------
__global__ void __launch_bounds__(PTPB) pre_kernel(
    const float* __restrict__ x, const float* __restrict__ c,
    const float* __restrict__ m1, const float* __restrict__ v1,
    const float* __restrict__ lg1, const float* __restrict__ be1,
    const float* __restrict__ Wg0, const float* __restrict__ bg0, const float* __restrict__ Wb0,
    const float* __restrict__ Wg1, const float* __restrict__ bg1, const float* __restrict__ Wb1,
    const float* __restrict__ Wg2, const float* __restrict__ bg2, const float* __restrict__ Wb2,
    const float* __restrict__ Wg3, const float* __restrict__ bg3, const float* __restrict__ Wb3)
{
    __shared__ float cs[PMT][Cc];
    int tid = threadIdx.x;
    int base = blockIdx.x * PMT;
    for (int i = tid; i < PMT*Cc; i += PTPB) cs[i>>6][i&63] = c[base*Cc + i];
    if (tid < PMT*Dd) {
        int m = tid/Dd, d = tid - m*Dd, p = base+m;
        g_xs[p*Dd+d] = (x[p*Dd+d] - m1[d]) * __expf(lg1[d]) * rsqrtf(v1[d]+EPSBN) + be1[d];
    }
    if (tid >= 64 && tid < 64+PMT) {
        int m = tid-64, p = base+m;
        float ld = 0.f;
        #pragma unroll
        for (int d = 0; d < Dd; ++d) ld += lg1[d] - 0.5f*logf(v1[d]+EPSBN);
        g_lp[p] = -ld;
    }
    __syncthreads();

    const float* WGs[3] = {Wg0, Wg1, Wg2};
    const float* BGs[3] = {bg0, bg1, bg2};
    const float* WBs[3] = {Wb0, Wb1, Wb2};
    float* GCs[3] = {g_Gc0, g_Gc1, g_Gc2};
    float* BCs[3] = {g_Bc0, g_Bc1, g_Bc2};
    #pragma unroll
    for (int l = 0; l < 3; ++l) {
        const float* Wg = WGs[l]; const float* Wb = WBs[l];
        #pragma unroll
        for (int s = 0; s < 2; ++s) {
            int j = tid + s*PTPB;
            float ag[PMT], ab[PMT];
            #pragma unroll
            for (int m = 0; m < PMT; ++m) { ag[m]=0.f; ab[m]=0.f; }
            const float* wgr = Wg + j*(Cc+1) + 1;
            const float* wbr = Wb + j*(Cc+1) + 1;
            for (int q = 0; q < Cc; ++q) {
                float a = wgr[q], b = wbr[q];
                #pragma unroll
                for (int m = 0; m < PMT; ++m) { ag[m] += a*cs[m][q]; ab[m] += b*cs[m][q]; }
            }
            float bgj = BGs[l][j];
            float* Gc = GCs[l]; float* Bc = BCs[l];
            for (int m = 0; m < PMT; ++m) {
                int p = base+m;
                Gc[p*HH+j] = ag[m]+bgj; Bc[p*HH+j] = ab[m];
            }
        }
    }
    if (tid < Dd) {
        int j = tid;
        float ag[PMT], ab[PMT];
        #pragma unroll
        for (int m = 0; m < PMT; ++m) { ag[m]=0.f; ab[m]=0.f; }
        const float* wgr = Wg3 + j*(Cc+1) + 1;
        const float* wbr = Wb3 + j*(Cc+1) + 1;
        for (int q = 0; q < Cc; ++q) {
            float a = wgr[q], b = wbr[q];
            #pragma unroll
            for (int m = 0; m < PMT; ++m) { ag[m] += a*cs[m][q]; ab[m] += b*cs[m][q]; }
        }
        for (int m = 0; m < PMT; ++m) {
            int p = base+m;
            g_Gc3[p*Dd+j] = ag[m]+bg3[j]; g_Bc3[p*Dd+j] = ab[m];
        }
    }
}

// ------------- fp16 TC GEMM (barrier-free internally) -------------
__device__ __forceinline__ void gemm_f16(const __half* __restrict__ Wp,
                                         uint32_t aB, float c[4][4][4], int tid)
{
    const int warp = tid>>5, lane = tid&31;
    const int g = lane>>2, tq = lane&3;
    const int arow = lane & 15, acolo = (lane>>4)*8;
    const __half* bp = Wp + (size_t)(warp*32 + g)*HH + tq*8;

    #pragma unroll 4
    for (int kp = 0; kp < 16; ++kp) {
        uint4 br[4];
        #pragma unroll
        for (int nt = 0; nt < 4; ++nt)
            br[nt] = *(const uint4*)(bp + (size_t)nt*8*HH + kp*32);
        #pragma unroll
        for (int h = 0; h < 2; ++h) {
            const int kc = 2*kp + h;
            uint32_t a[4][4];
            #pragma unroll
            for (int mt = 0; mt < 4; ++mt) {
                uint32_t addr = aB + (uint32_t)(((mt*16+arow)*ASH) + kc*16 + acolo)*2;
                LDSM4(a[mt][0], a[mt][1], a[mt][2], a[mt][3], addr);
            }
            #pragma unroll
            for (int nt = 0; nt < 4; ++nt) {
                uint32_t b0 = h ? br[nt].z : br[nt].x;
                uint32_t b1 = h ? br[nt].w : br[nt].y;
                #pragma unroll
                for (int mt = 0; mt < 4; ++mt)
                    mma_f16(c[mt][nt], a[mt][0], a[mt][1], a[mt][2], a[mt][3], b0, b1);
            }
        }
    }
}

// ------------- persistent flow kernel -------------
__global__ void __launch_bounds__(TPB, 1) flow_kernel(
    const float* __restrict__ W0, const float* __restrict__ b0,
    const float* __restrict__ Wg0, const float* __restrict__ Wb0,
    const float* __restrict__ b1,
    const float* __restrict__ Wg1, const float* __restrict__ Wb1,
    const float* __restrict__ b2,
    const float* __restrict__ Wg2, const float* __restrict__ Wb2,
    const float* __restrict__ W3, const float* __restrict__ b3,
    const float* __restrict__ Wg3, const float* __restrict__ Wb3,
    const float* __restrict__ sqrtT)
{
    extern __shared__ char smraw[];
    __half* Ah  = (__half*)smraw;            // 64*ASH halves
    float* gbuf = (float*)(Ah + 64*ASH);     // 2 * GBUF floats
    float* colc = gbuf + 2*GBUF;             // 9*512
    float* wred = colc + 9*HH;               // 16*96
    float* xin  = wred + 16*96;              // 48
    float* sdx  = xin + 48;
    float* pdg  = sdx + 48;
    float* xs_s = pdg + 48;
    float* ax_s = xs_s + 48;
    float* lp_s = ax_s + 48;                 // 16
    float* al_s = lp_s + 16;                 // 16

    const int tid = threadIdx.x;
    const int warp = tid>>5, lane = tid&31;
    const int g = lane>>2, tq = lane&3;
    const int nb = warp*32;
    const int base = blockIdx.x*MT;
    const uint32_t aB = (uint32_t)__cvta_generic_to_shared(Ah);
    const uint32_t gB = (uint32_t)__cvta_generic_to_shared(gbuf);
    const float sT = sqrtT[0];
    const float dt = sT*sT*(1.f/3.f);

    colc[0*HH+tid] = b1[tid];
    colc[1*HH+tid] = Wg1[tid*65];
    colc[2*HH+tid] = Wb1[tid*65];
    colc[3*HH+tid] = b2[tid];
    colc[4*HH+tid] = Wg2[tid*65];
    colc[5*HH+tid] = Wb2[tid*65];
    colc[6*HH+tid] = W3[tid];
    colc[7*HH+tid] = W3[HH+tid];
    colc[8*HH+tid] = W3[2*HH+tid];
    if (tid < MT*Dd) { float v = g_xs[base*Dd + tid]; xin[tid] = v; xs_s[tid] = v; }
    if (tid < MT) lp_s[tid] = g_lp[base + tid];

    // loop-invariant L0 per-column constants
    const int j = tid;
    const float wa = W0[j*3], wb = W0[j*3+1], wc = W0[j*3+2];
    const float bj = b0[j], wgt = Wg0[j*65], wbt = Wb0[j*65];

    pf_pair(gB, g_Gc0 + (size_t)base*HH, g_Bc0 + (size_t)base*HH, tid); CPC();
    CPW0();
    __syncthreads();

    int ping = 0;
    for (int it = 0; it < 12; ++it) {
        const int s = it & 3;
        const float tc = (s == 0) ? 0.f : ((s == 3) ? 1.f : 0.5f);
        const float t = ((float)(it >> 2) + tc) * dt;
        float* bufL = gbuf + ping*GBUF;
        float* bufE = gbuf + (1-ping)*GBUF;
        uint32_t bufLB = gB + ping*GBUF*4;
        uint32_t bufEB = gB + (1-ping)*GBUF*4;

        // ---- L0 ----
        {
            float twg = t*wgt, twb = t*wbt;
            #pragma unroll 4
            for (int m = 0; m < MT; ++m) {
                float z = xin[m*3]*wa + xin[m*3+1]*wb + xin[m*3+2]*wc + bj;
                float gg = sigf(twg + bufL[m*GSH + j]);
                float hv = htanh(z*gg + twb + bufL[(16+m)*GSH + j]);
                float qq = (1.f - hv*hv)*gg;
                Ah[m*ASH + j]      = __float2half_rn(hv);
                Ah[(16+m)*ASH + j] = __float2half_rn(qq*wa);
                Ah[(32+m)*ASH + j] = __float2half_rn(qq*wb);
                Ah[(48+m)*ASH + j] = __float2half_rn(qq*wc);
            }
        }
        pf_pair(bufEB, g_Gc1 + (size_t)base*HH, g_Bc1 + (size_t)base*HH, tid); CPC();
        __syncthreads();

        float c[4][4][4];
        #pragma unroll
        for (int a1=0;a1<4;++a1) for (int a2=0;a2<4;++a2) for (int a3=0;a3<4;++a3) c[a1][a2][a3]=0.f;
        gemm_f16(g_W1p, aB, c, tid);
        CPW0();
        __syncthreads();

        // ---- EW1 ----
        #pragma unroll
        for (int nt = 0; nt < 4; ++nt) {
            int col0 = nb + nt*8 + 2*tq;
            float bc0 = colc[0*HH+col0], bc1 = colc[0*HH+col0+1];
            float wg0 = colc[1*HH+col0], wg1v = colc[1*HH+col0+1];
            float wb0 = colc[2*HH+col0], wb1v = colc[2*HH+col0+1];
            #pragma unroll
            for (int kh = 0; kh < 2; ++kh) {
                int m = g + kh*8;
                float2 gc = *(const float2*)&bufE[m*GSH + col0];
                float2 bc = *(const float2*)&bufE[(16+m)*GSH + col0];
                float gate0 = sigf(t*wg0 + gc.x);
                float gate1 = sigf(t*wg1v + gc.y);
                float h0 = htanh((c[0][nt][kh*2]  +bc0)*gate0 + t*wb0  + bc.x);
                float h1 = htanh((c[0][nt][kh*2+1]+bc1)*gate1 + t*wb1v + bc.y);
                float q0 = (1.f-h0*h0)*gate0, q1 = (1.f-h1*h1)*gate1;
                *(__half2*)(Ah + m*ASH + col0) = __floats2half2_rn(h0, h1);
                #pragma unroll
                for (int d = 0; d < 3; ++d)
                    *(__half2*)(Ah + (16+16*d+m)*ASH + col0) =
                        __floats2half2_rn(c[1+d][nt][kh*2]*q0, c[1+d][nt][kh*2+1]*q1);
            }
        }
        pf_pair(bufLB, g_Gc2 + (size_t)base*HH, g_Bc2 + (size_t)base*HH, tid); CPC();
        __syncthreads();

        #pragma unroll
        for (int a1=0;a1<4;++a1) for (int a2=0;a2<4;++a2) for (int a3=0;a3<4;++a3) c[a1][a2][a3]=0.f;
        gemm_f16(g_W2p, aB, c, tid);
        CPW0();
        __syncthreads();

        // ---- EW2 + reductions ----
        {
            float v[12];
            #pragma unroll
            for (int k = 0; k < 12; ++k) v[k] = 0.f;
            #pragma unroll
            for (int nt = 0; nt < 4; ++nt) {
                int col0 = nb + nt*8 + 2*tq;
                float bc0 = colc[3*HH+col0], bc1 = colc[3*HH+col0+1];
                float wg0 = colc[4*HH+col0], wg1v = colc[4*HH+col0+1];
                float wb0 = colc[5*HH+col0], wb1v = colc[5*HH+col0+1];
                float2 w3p[3];
                #pragma unroll
                for (int d = 0; d < 3; ++d) w3p[d] = *(const float2*)&colc[(6+d)*HH+col0];
                #pragma unroll
                for (int kh = 0; kh < 2; ++kh) {
                    int m = g + kh*8;
                    float2 gc = *(const float2*)&bufL[m*GSH + col0];
                    float2 bc = *(const float2*)&bufL[(16+m)*GSH + col0];
                    float gate0 = sigf(t*wg0 + gc.x);
                    float gate1 = sigf(t*wg1v + gc.y);
                    float h0 = htanh((c[0][nt][kh*2]  +bc0)*gate0 + t*wb0  + bc.x);
                    float h1 = htanh((c[0][nt][kh*2+1]+bc1)*gate1 + t*wb1v + bc.y);
                    float q0 = (1.f-h0*h0)*gate0, q1 = (1.f-h1*h1)*gate1;
                    #pragma unroll
                    for (int d = 0; d < 3; ++d) {
                        v[kh*6+d]   += h0*w3p[d].x + h1*w3p[d].y;
                        v[kh*6+3+d] += q0*w3p[d].x*c[1+d][nt][kh*2]
                                     + q1*w3p[d].y*c[1+d][nt][kh*2+1];
                    }
                }
            }
            #pragma unroll
            for (int k = 0; k < 12; ++k) {
                v[k] += __shfl_xor_sync(0xffffffffu, v[k], 1);
                v[k] += __shfl_xor_sync(0xffffffffu, v[k], 2);
            }
            if (tq == 0) {
                #pragma unroll
                for (int k = 0; k < 6; ++k) {
                    wred[warp*96 + g*6 + k]     = v[k];
                    wred[warp*96 + (g+8)*6 + k] = v[6+k];
                }
            }
        }
        if (it < 11) {
            pf_pair(bufEB, g_Gc0 + (size_t)base*HH, g_Bc0 + (size_t)base*HH, tid); CPC();
        }
        __syncthreads();

        if (tid < 96) {
            int m = tid/6, k = tid - m*6;
            float sv = 0.f;
            #pragma unroll
            for (int w = 0; w < 16; ++w) sv += wred[w*96 + tid];
            int p = base + m;
            if (k < 3) {
                int d = k;
                float g3 = sigf(t*Wg3[d*65] + g_Gc3[p*3+d]);
                sdx[m*3+d] = (sv + b3[d])*g3 + t*Wb3[d*65] + g_Bc3[p*3+d];
            } else {
                int d = k-3;
                float g3 = sigf(t*Wg3[d*65] + g_Gc3[p*3+d]);
                pdg[m*3+d] = sv*g3;
            }
        }
        __syncthreads();

        if (tid < MT) {
            int m = tid;
            float kl = -(pdg[m*3] + pdg[m*3+1] + pdg[m*3+2]);
            if (s == 0) {
                al_s[m] = kl;
                #pragma unroll
                for (int d = 0; d < 3; ++d) {
                    float kx = sdx[m*3+d];
                    ax_s[m*3+d] = kx;
                    xin[m*3+d] = xs_s[m*3+d] + 0.5f*dt*kx;
                }
            } else if (s == 1) {
                al_s[m] += 2.f*kl;
                #pragma unroll
                for (int d = 0; d < 3; ++d) {
                    float kx = sdx[m*3+d];
                    ax_s[m*3+d] += 2.f*kx;
                    xin[m*3+d] = xs_s[m*3+d] + 0.5f*dt*kx;
                }
            } else if (s == 2) {
                al_s[m] += 2.f*kl;
                #pragma unroll
                for (int d = 0; d < 3; ++d) {
                    float kx = sdx[m*3+d];
                    ax_s[m*3+d] += 2.f*kx;
                    xin[m*3+d] = xs_s[m*3+d] + dt*kx;
                }
            } else {
                float c6 = dt*(1.f/6.f);
                lp_s[m] += c6*(al_s[m] + kl);
                #pragma unroll
                for (int d = 0; d < 3; ++d) {
                    float nv = xs_s[m*3+d] + c6*(ax_s[m*3+d] + sdx[m*3+d]);
                    xs_s[m*3+d] = nv;
                    xin[m*3+d] = nv;
                }
            }
        }
        if (it < 11) CPW0();
        __syncthreads();
        ping ^= 1;
    }

    if (tid < MT*Dd) g_xs[base*Dd + tid] = xs_s[tid];
    if (tid < MT) g_lp[base + tid] = lp_s[tid];
}

// ------------- bn2 + per-batch logp reduction + output -------------
__global__ void __launch_bounds__(PTPB) final_kernel(
    const float* __restrict__ m2, const float* __restrict__ v2,
    const float* __restrict__ lg2, const float* __restrict__ be2,
    float* __restrict__ out)
{
    __shared__ float red[PTPB];
    int b = blockIdx.x, tid = threadIdx.x;
    float sc[3], mn[3], bt[3];
    float ld2 = 0.f;
    #pragma unroll
    for (int d = 0; d < 3; ++d) {
        sc[d] = __expf(lg2[d]) * rsqrtf(v2[d]+EPSBN);
        mn[d] = m2[d]; bt[d] = be2[d];
        ld2 += lg2[d] - 0.5f*logf(v2[d]+EPSBN);
    }
    float part = 0.f;
    for (int n = tid; n < NPTS; n += PTPB) {
        int p = b*NPTS + n;
        #pragma unroll
        for (int d = 0; d < 3; ++d)
            out[p*3+d] = (g_xs[p*3+d]-mn[d])*sc[d] + bt[d];
        part += g_lp[p] - ld2;
    }
    red[tid] = part;
    __syncthreads();
    for (int off = PTPB/2; off > 0; off >>= 1) {
        if (tid < off) red[tid] += red[tid+off];
        __syncthreads();
    }
    if (tid == 0) out[P*3 + b] = red[0];
}

// ---------------- launch ----------------
extern "C" void kernel_launch(void* const* d_in, const int* in_sizes, int n_in,
                              void* d_out, int out_size)
{
    const float* x    = (const float*)d_in[0];
    const float* c    = (const float*)d_in[1];
    const float* bn1m = (const float*)d_in[2];
    const float* bn1v = (const float*)d_in[3];
    const float* bn1g = (const float*)d_in[4];
    const float* bn1b = (const float*)d_in[5];
    const float* bn2m = (const float*)d_in[6];
    const float* bn2v = (const float*)d_in[7];
    const float* bn2g = (const float*)d_in[8];
    const float* bn2b = (const float*)d_in[9];
    const float* sqT  = (const float*)d_in[10];
    const float *W[4], *bb[4], *Wg[4], *bg[4], *Wb[4];
    for (int i = 0; i < 4; ++i) {
        W[i]  = (const float*)d_in[11+5*i];
        bb[i] = (const float*)d_in[12+5*i];
        Wg[i] = (const float*)d_in[13+5*i];
        bg[i] = (const float*)d_in[14+5*i];
        Wb[i] = (const float*)d_in[15+5*i];
    }

    int smem = (64*ASH)*2 + (2*GBUF + 9*HH + 16*96 + 48*5 + 16*2)*4;
    cudaFuncSetAttribute(flow_kernel, cudaFuncAttributeMaxDynamicSharedMemorySize, smem);

    conv_kernel<<<HH*HH/TPB, TPB>>>(W[1], W[2]);
    pre_kernel<<<PGRID, PTPB>>>(x, c, bn1m, bn1v, bn1g, bn1b,
                                Wg[0], bg[0], Wb[0], Wg[1], bg[1], Wb[1],
                                Wg[2], bg[2], Wb[2], Wg[3], bg[3], Wb[3]);
    flow_kernel<<<GRID, TPB, smem>>>(
        W[0], bb[0], Wg[0], Wb[0],
        bb[1], Wg[1], Wb[1],
        bb[2], Wg[2], Wb[2],
        W[3], bb[3], Wg[3], Wb[3],
        sqT);
    final_kernel<<<NB, PTPB>>>(bn2m, bn2v, bn2g, bn2b, (float*)d_out);
}